// round 8
// baseline (speedup 1.0000x reference)
#include <cuda_runtime.h>

#define B_  128
#define N_  512
#define D_  300
#define NC_ 10
#define DC_ 64
#define M_  640   // NC_*DC_

// Scratch (device globals; allocation-free per harness rules)
__device__ __align__(16) float g_y0p[B_*4*D_];    // colsum partials [B][4][D]
__device__ __align__(16) float g_v[B_*NC_*D_];    // v = log2e * W_i o_i  [B][NC][D]
__device__ __align__(16) float g_y[B_*NC_*D_];    // y = sum c x          [B][NC][D]
__device__ __align__(16) float g_Wt[M_*D_];       // W transposed [M][D]

// ---- packed f32x2 FMA (PTX-only; ptxas never auto-fuses) -------------------
__device__ __forceinline__ float2 ffma2(float2 a, float2 b, float2 c) {
    float2 d;
    asm("fma.rn.f32x2 %0, %1, %2, %3;"
        : "=l"(*reinterpret_cast<unsigned long long*>(&d))
        : "l"(*reinterpret_cast<const unsigned long long*>(&a)),
          "l"(*reinterpret_cast<const unsigned long long*>(&b)),
          "l"(*reinterpret_cast<const unsigned long long*>(&c)));
    return d;
}
// ---- raw MUFU ops (library exp2f/frcp are multi-instr without fast-math) ---
__device__ __forceinline__ float ex2_approx(float x) {
    float r; asm("ex2.approx.f32 %0, %1;" : "=f"(r) : "f"(x)); return r;
}
__device__ __forceinline__ float rcp_approx(float x) {
    float r; asm("rcp.approx.f32 %0, %1;" : "=f"(r) : "f"(x)); return r;
}

// ---------------------------------------------------------------------------
// Kernel 0: one-time W transpose  Wt[m][d] = W[d][m]
// ---------------------------------------------------------------------------
__global__ void k_transpose(const float* __restrict__ W) {
    __shared__ float t[32][33];
    const int mx = blockIdx.x*32, dy = blockIdx.y*32;
    #pragma unroll
    for (int r = 0; r < 4; ++r) {
        const int d = dy + threadIdx.y + 8*r;
        if (d < D_) t[threadIdx.y + 8*r][threadIdx.x] = W[(size_t)d*M_ + mx + threadIdx.x];
    }
    __syncthreads();
    #pragma unroll
    for (int r = 0; r < 4; ++r) {
        const int m = mx + threadIdx.y + 8*r;
        const int d = dy + threadIdx.x;
        if (d < D_) g_Wt[(size_t)m*D_ + d] = t[threadIdx.x][threadIdx.y + 8*r];
    }
}

// ---------------------------------------------------------------------------
// Kernel 1: per-batch column sums of x (iteration-0 y is 0.1 * colsum)
// ---------------------------------------------------------------------------
__global__ void k_colsum(const float* __restrict__ x) {
    const int b = blockIdx.x, q = blockIdx.y;
    const float* xb = x + (size_t)(b*N_ + q*128)*D_;
    for (int d = threadIdx.x; d < D_; d += blockDim.x) {
        float a0=0.f, a1=0.f, a2=0.f, a3=0.f;
        #pragma unroll 4
        for (int r = 0; r < 128; r += 4) {
            a0 += xb[(size_t)(r+0)*D_ + d];
            a1 += xb[(size_t)(r+1)*D_ + d];
            a2 += xb[(size_t)(r+2)*D_ + d];
            a3 += xb[(size_t)(r+3)*D_ + d];
        }
        g_y0p[(b*4 + q)*D_ + d] = (a0+a1)+(a2+a3);
    }
}

// ---------------------------------------------------------------------------
// Kernel 2: capsule reduce (W stays L2-resident; no W smem).
//   y -> s = W_i^T y -> o = squash(s) -> v = log2e * W_i o
// grid (NC, B/4) = (10,32), 256 threads, b-tile 4.
// ---------------------------------------------------------------------------
__global__ void __launch_bounds__(256) k_caps(const float* __restrict__ W,
                                              float* __restrict__ out, int phase) {
    __shared__ float ys[4][304];
    __shared__ float sp[4][4][64];   // [h][b][k] S-phase partials
    __shared__ float os[4][64];
    __shared__ float qw[8];
    const int i   = blockIdx.x;
    const int bt  = blockIdx.y*4;
    const int tid = threadIdx.x;

    if (phase == 0) {
        #pragma unroll
        for (int bb = 0; bb < 4; ++bb)
            for (int d = tid; d < D_; d += 256) {
                const float* p = g_y0p + (size_t)(bt+bb)*4*D_ + d;
                ys[bb][d] = 0.1f*((p[0] + p[D_]) + (p[2*D_] + p[3*D_]));
            }
    } else {
        #pragma unroll
        for (int bb = 0; bb < 4; ++bb)
            for (int d = tid; d < D_; d += 256)
                ys[bb][d] = g_y[((size_t)(bt+bb)*NC_ + i)*D_ + d];
    }
    __syncthreads();

    // S phase: thread (k = tid&63, h = tid>>6) covers d in [75h, 75h+75)
    {
        const int k = tid & 63, h = tid >> 6;
        const float* wp = W + (size_t)(75*h)*M_ + i*DC_ + k;
        float a0=0.f, a1=0.f, a2=0.f, a3=0.f;
        #pragma unroll 5
        for (int dd = 0; dd < 75; ++dd) {
            const float wv = wp[(size_t)dd*M_];
            const int d = 75*h + dd;
            a0 = fmaf(wv, ys[0][d], a0);
            a1 = fmaf(wv, ys[1][d], a1);
            a2 = fmaf(wv, ys[2][d], a2);
            a3 = fmaf(wv, ys[3][d], a3);
        }
        sp[h][0][k] = a0; sp[h][1][k] = a1; sp[h][2][k] = a2; sp[h][3][k] = a3;
    }
    __syncthreads();

    // combine + squash: thread tid -> (b = tid>>6, k = tid&63)
    {
        const int b = tid >> 6, k = tid & 63;
        const float s = (sp[0][b][k] + sp[1][b][k]) + (sp[2][b][k] + sp[3][b][k]);
        float q = s*s;
        #pragma unroll
        for (int off = 16; off; off >>= 1) q += __shfl_xor_sync(0xffffffffu, q, off);
        const int w = tid >> 5;
        if ((tid & 31) == 0) qw[w] = q;
        __syncthreads();
        const float ri = rsqrtf(qw[2*b] + qw[2*b+1] + 1e-7f);
        const float o = s * ri;
        os[b][k] = o;
        if (phase == 2) out[((size_t)(bt+b)*NC_ + i)*DC_ + k] = o;
    }
    __syncthreads();

    // V phase: v[b][d] = log2e * sum_k Wt[i*64+k][d] * o[b][k]
    if (phase != 2) {
        const float L2E = 1.44269504f;
        for (int d = tid; d < D_; d += 256) {
            const float* wt = g_Wt + (size_t)(i*DC_)*D_ + d;
            float a0=0.f, a1=0.f, a2=0.f, a3=0.f;
            #pragma unroll 8
            for (int k = 0; k < 64; ++k) {
                const float wv = wt[(size_t)k*D_];
                a0 = fmaf(wv, os[0][k], a0);
                a1 = fmaf(wv, os[1][k], a1);
                a2 = fmaf(wv, os[2][k], a2);
                a3 = fmaf(wv, os[3][k], a3);
            }
            g_v[((size_t)(bt+0)*NC_ + i)*D_ + d] = a0 * L2E;
            g_v[((size_t)(bt+1)*NC_ + i)*D_ + d] = a1 * L2E;
            g_v[((size_t)(bt+2)*NC_ + i)*D_ + d] = a2 * L2E;
            g_v[((size_t)(bt+3)*NC_ + i)*D_ + d] = a3 * L2E;
        }
    }
}

// ---------------------------------------------------------------------------
// Kernel 3 (v3): main routing pass. grid (B), 384 threads (12 warps).
// v lives in SMEM (padded stride 320, zero-padded tail) -> frees ~100 regs
// -> 3 warps/SMSP. ILP-2 rows amortizes each v-LDS over 2 rows.
// Warp w owns rows [beg,end): 43 rows for w<8, 42 for w>=8.
// ---------------------------------------------------------------------------
#define VSTR 320
__global__ void __launch_bounds__(384, 1) k_main(const float* __restrict__ x) {
    extern __shared__ float sm[];
    float* vs   = sm;             // [NC_][VSTR]  12.8 KB
    float* slab = sm + NC_*VSTR;  // [6][NC_][D_] 72 KB  cross-warp y merge
    const int b    = blockIdx.x;
    const int tid  = threadIdx.x;
    const int w    = tid >> 5;
    const int lane = tid & 31;
    const bool tl22 = (lane < 22);

    // stage v (pre-scaled by log2e in k_caps) into smem; zero the padding
    {
        const float* vb = g_v + (size_t)b*NC_*D_;
        for (int idx = tid; idx < NC_*D_; idx += 384) {
            const int i = idx / D_, d = idx - i*D_;
            vs[i*VSTR + d] = vb[idx];
        }
        for (int idx = tid; idx < NC_*(VSTR - D_); idx += 384) {
            const int i = idx / (VSTR - D_), p = idx - i*(VSTR - D_);
            vs[i*VSTR + D_ + p] = 0.f;
        }
    }
    __syncthreads();

    float2 yr[NC_][5];
    #pragma unroll
    for (int i = 0; i < NC_; ++i)
        #pragma unroll
        for (int t = 0; t < 5; ++t) yr[i][t] = make_float2(0.f, 0.f);

    const int beg = (w < 8) ? w*43 : 344 + (w - 8)*42;
    const int end = (w < 8) ? beg + 43 : beg + 42;
    const float* xb = x + (size_t)b*N_*D_;

    int j = beg;
    for (; j + 1 < end; j += 2) {
        const float* xrA = xb + (size_t)j*D_;
        const float* xrB = xrA + D_;
        float2 xqA[5], xqB[5];
        #pragma unroll
        for (int t = 0; t < 4; ++t) {
            xqA[t] = *(const float2*)(xrA + 2*lane + 64*t);
            xqB[t] = *(const float2*)(xrB + 2*lane + 64*t);
        }
        xqA[4] = tl22 ? *(const float2*)(xrA + 2*lane + 256) : make_float2(0.f, 0.f);
        xqB[4] = tl22 ? *(const float2*)(xrB + 2*lane + 256) : make_float2(0.f, 0.f);

        float tlA[NC_], tlB[NC_];
        #pragma unroll
        for (int i = 0; i < NC_; ++i) {
            float2 aA = make_float2(0.f, 0.f), aB = make_float2(0.f, 0.f);
            #pragma unroll
            for (int t = 0; t < 5; ++t) {
                const float2 vv = *(const float2*)(vs + i*VSTR + 2*lane + 64*t);
                aA = ffma2(xqA[t], vv, aA);
                aB = ffma2(xqB[t], vv, aB);
            }
            tlA[i] = aA.x + aA.y;
            tlB[i] = aB.x + aB.y;
        }
        #pragma unroll
        for (int off = 16; off; off >>= 1) {
            #pragma unroll
            for (int i = 0; i < NC_; ++i) {
                tlA[i] += __shfl_xor_sync(0xffffffffu, tlA[i], off);
                tlB[i] += __shfl_xor_sync(0xffffffffu, tlB[i], off);
            }
        }
        #pragma unroll
        for (int i = 0; i < NC_; ++i) { tlA[i] = ex2_approx(tlA[i]); tlB[i] = ex2_approx(tlB[i]); }
        float sA = (((tlA[0]+tlA[1])+(tlA[2]+tlA[3]))+((tlA[4]+tlA[5])+(tlA[6]+tlA[7])))+(tlA[8]+tlA[9]);
        float sB = (((tlB[0]+tlB[1])+(tlB[2]+tlB[3]))+((tlB[4]+tlB[5])+(tlB[6]+tlB[7])))+(tlB[8]+tlB[9]);
        const float rA = rcp_approx(sA), rB = rcp_approx(sB);
        #pragma unroll
        for (int i = 0; i < NC_; ++i) {
            const float2 cA = make_float2(tlA[i]*rA, tlA[i]*rA);
            const float2 cB = make_float2(tlB[i]*rB, tlB[i]*rB);
            #pragma unroll
            for (int t = 0; t < 5; ++t)
                yr[i][t] = ffma2(cB, xqB[t], ffma2(cA, xqA[t], yr[i][t]));
        }
    }
    if (j < end) {                                  // odd-count tail row
        const float* xr = xb + (size_t)j*D_;
        float2 xq[5];
        #pragma unroll
        for (int t = 0; t < 4; ++t) xq[t] = *(const float2*)(xr + 2*lane + 64*t);
        xq[4] = tl22 ? *(const float2*)(xr + 2*lane + 256) : make_float2(0.f, 0.f);
        float tl[NC_];
        #pragma unroll
        for (int i = 0; i < NC_; ++i) {
            float2 a = make_float2(0.f, 0.f);
            #pragma unroll
            for (int t = 0; t < 5; ++t) {
                const float2 vv = *(const float2*)(vs + i*VSTR + 2*lane + 64*t);
                a = ffma2(xq[t], vv, a);
            }
            tl[i] = a.x + a.y;
        }
        #pragma unroll
        for (int off = 16; off; off >>= 1)
            #pragma unroll
            for (int i = 0; i < NC_; ++i)
                tl[i] += __shfl_xor_sync(0xffffffffu, tl[i], off);
        #pragma unroll
        for (int i = 0; i < NC_; ++i) tl[i] = ex2_approx(tl[i]);
        float s = (((tl[0]+tl[1])+(tl[2]+tl[3]))+((tl[4]+tl[5])+(tl[6]+tl[7])))+(tl[8]+tl[9]);
        const float r = rcp_approx(s);
        #pragma unroll
        for (int i = 0; i < NC_; ++i) {
            const float2 c = make_float2(tl[i]*r, tl[i]*r);
            #pragma unroll
            for (int t = 0; t < 5; ++t) yr[i][t] = ffma2(c, xq[t], yr[i][t]);
        }
    }

    // merge 12 warp partials: warps 0-5 store slabs, warps 6-11 add into them
    if (w < 6) {
        #pragma unroll
        for (int i = 0; i < NC_; ++i)
            #pragma unroll
            for (int t = 0; t < 5; ++t) {
                const int d = 2*lane + 64*t;
                if (d < D_) *(float2*)&slab[(w*NC_ + i)*D_ + d] = yr[i][t];
            }
    }
    __syncthreads();
    if (w >= 6) {
        #pragma unroll
        for (int i = 0; i < NC_; ++i)
            #pragma unroll
            for (int t = 0; t < 5; ++t) {
                const int d = 2*lane + 64*t;
                if (d < D_) {
                    float2* p = (float2*)&slab[((w-6)*NC_ + i)*D_ + d];
                    float2 v0 = *p;
                    v0.x += yr[i][t].x; v0.y += yr[i][t].y;
                    *p = v0;
                }
            }
    }
    __syncthreads();
    float* yo = g_y + (size_t)b*NC_*D_;
    for (int idx = tid; idx < NC_*D_; idx += 384) {
        const float v0 = slab[idx]           + slab[NC_*D_   + idx];
        const float v1 = slab[2*NC_*D_ + idx] + slab[3*NC_*D_ + idx];
        const float v2 = slab[4*NC_*D_ + idx] + slab[5*NC_*D_ + idx];
        yo[idx] = (v0 + v1) + v2;
    }
}

// ---------------------------------------------------------------------------
extern "C" void kernel_launch(void* const* d_in, const int* in_sizes, int n_in,
                              void* d_out, int out_size) {
    const float* x = (const float*)d_in[0];
    const float* W = (const float*)d_in[1];
    if (n_in >= 2 && in_sizes[0] == D_*M_) {    // guard against input-order swap
        x = (const float*)d_in[1];
        W = (const float*)d_in[0];
    }
    float* out = (float*)d_out;

    const int MAIN_SMEM = (NC_*VSTR + 6*NC_*D_) * (int)sizeof(float);  // ~84.8 KB
    cudaFuncSetAttribute(k_main, cudaFuncAttributeMaxDynamicSharedMemorySize, MAIN_SMEM);

    k_transpose<<<dim3(M_/32, (D_+31)/32), dim3(32, 8)>>>(W);
    // iter 0: c uniform (=0.1) -> y = 0.1*colsum -> o0, v0
    k_colsum<<<dim3(B_, 4), 256>>>(x);
    k_caps<<<dim3(NC_, B_/4), 256>>>(W, out, 0);
    // iters 1..4: b = x.v -> softmax -> y;  y -> o -> v  (iter 4 writes output)
    for (int it = 1; it <= 4; ++it) {
        k_main<<<B_, 384, MAIN_SMEM>>>(x);
        k_caps<<<dim3(NC_, B_/4), 256>>>(W, out, it == 4 ? 2 : 1);
    }
}

// round 9
// speedup vs baseline: 1.3356x; 1.3356x over previous
#include <cuda_runtime.h>

#define B_  128
#define N_  512
#define D_  300
#define NC_ 10
#define DC_ 64
#define M_  640   // NC_*DC_
#define GMAIN 148 // k_main blocks (SM-count safe: never a 2nd wave on >=148 SMs)
#define RTOT (B_*N_)

// Scratch (device globals; allocation-free per harness rules)
__device__ __align__(16) float g_y0p[B_*4*D_];    // colsum partials [B][4][D]
__device__ __align__(16) float g_v[B_*NC_*D_];    // v = log2e * W_i o_i  [B][NC][D]
__device__ __align__(16) float g_y[B_*NC_*D_];    // y accum (atomic)     [B][NC][D]
__device__ __align__(16) float g_Wt[M_*D_];       // W transposed [M][D]

// ---- packed f32x2 FMA (PTX-only; ptxas never auto-fuses) -------------------
__device__ __forceinline__ float2 ffma2(float2 a, float2 b, float2 c) {
    float2 d;
    asm("fma.rn.f32x2 %0, %1, %2, %3;"
        : "=l"(*reinterpret_cast<unsigned long long*>(&d))
        : "l"(*reinterpret_cast<const unsigned long long*>(&a)),
          "l"(*reinterpret_cast<const unsigned long long*>(&b)),
          "l"(*reinterpret_cast<const unsigned long long*>(&c)));
    return d;
}
// ---- raw MUFU ops (library exp2f/frcp are multi-instr without fast-math) ---
__device__ __forceinline__ float ex2_approx(float x) {
    float r; asm("ex2.approx.f32 %0, %1;" : "=f"(r) : "f"(x)); return r;
}
__device__ __forceinline__ float rcp_approx(float x) {
    float r; asm("rcp.approx.f32 %0, %1;" : "=f"(r) : "f"(x)); return r;
}

// ---------------------------------------------------------------------------
// Kernel 0 (fused prep): bid<512 -> colsum block; else W transpose tile.
// 256 threads both paths.
// ---------------------------------------------------------------------------
__global__ void k_prep(const float* __restrict__ x, const float* __restrict__ W) {
    const int bid = blockIdx.x;
    const int tid = threadIdx.x;
    if (bid < 512) {                       // colsum: b = bid>>2, quarter = bid&3
        const int b = bid >> 2, q = bid & 3;
        const float* xb = x + (size_t)(b*N_ + q*128)*D_;
        for (int d = tid; d < D_; d += 256) {
            float a0=0.f, a1=0.f, a2=0.f, a3=0.f;
            #pragma unroll 4
            for (int r = 0; r < 128; r += 4) {
                a0 += xb[(size_t)(r+0)*D_ + d];
                a1 += xb[(size_t)(r+1)*D_ + d];
                a2 += xb[(size_t)(r+2)*D_ + d];
                a3 += xb[(size_t)(r+3)*D_ + d];
            }
            g_y0p[(b*4 + q)*D_ + d] = (a0+a1)+(a2+a3);
        }
    } else {                               // transpose tile
        __shared__ float t[32][33];
        const int tt = bid - 512;          // 0..199
        const int mx = (tt % 20)*32, dy = (tt / 20)*32;
        const int tx = tid & 31, ty = tid >> 5;
        #pragma unroll
        for (int r = 0; r < 4; ++r) {
            const int d = dy + ty + 8*r;
            if (d < D_) t[ty + 8*r][tx] = W[(size_t)d*M_ + mx + tx];
        }
        __syncthreads();
        #pragma unroll
        for (int r = 0; r < 4; ++r) {
            const int m = mx + ty + 8*r;
            const int d = dy + tx;
            if (d < D_) g_Wt[(size_t)m*D_ + d] = t[tx][ty + 8*r];
        }
    }
}

// ---------------------------------------------------------------------------
// Kernel 2: capsule reduce (W stays L2-resident; no W smem).
//   y -> s = W_i^T y -> o = squash(s) -> v = log2e * W_i o
// grid (NC, B/4) = (10,32), 256 threads, b-tile 4.
// Zeroes its g_y region after consuming it (phases 0,1) so k_main can
// accumulate the next iteration with gmem atomics.
// ---------------------------------------------------------------------------
__global__ void __launch_bounds__(256) k_caps(const float* __restrict__ W,
                                              float* __restrict__ out, int phase) {
    __shared__ float ys[4][304];
    __shared__ float sp[4][4][64];   // [h][b][k] S-phase partials
    __shared__ float os[4][64];
    __shared__ float qw[8];
    const int i   = blockIdx.x;
    const int bt  = blockIdx.y*4;
    const int tid = threadIdx.x;

    if (phase == 0) {
        #pragma unroll
        for (int bb = 0; bb < 4; ++bb)
            for (int d = tid; d < D_; d += 256) {
                const float* p = g_y0p + (size_t)(bt+bb)*4*D_ + d;
                ys[bb][d] = 0.1f*((p[0] + p[D_]) + (p[2*D_] + p[3*D_]));
                g_y[((size_t)(bt+bb)*NC_ + i)*D_ + d] = 0.f;   // init accum
            }
    } else {
        #pragma unroll
        for (int bb = 0; bb < 4; ++bb)
            for (int d = tid; d < D_; d += 256) {
                float* yp = &g_y[((size_t)(bt+bb)*NC_ + i)*D_ + d];
                ys[bb][d] = *yp;
                if (phase == 1) *yp = 0.f;   // same thread read->zero: race-free
            }
    }
    __syncthreads();

    // S phase: thread (k = tid&63, h = tid>>6) covers d in [75h, 75h+75)
    {
        const int k = tid & 63, h = tid >> 6;
        const float* wp = W + (size_t)(75*h)*M_ + i*DC_ + k;
        float a0=0.f, a1=0.f, a2=0.f, a3=0.f;
        #pragma unroll 5
        for (int dd = 0; dd < 75; ++dd) {
            const float wv = wp[(size_t)dd*M_];
            const int d = 75*h + dd;
            a0 = fmaf(wv, ys[0][d], a0);
            a1 = fmaf(wv, ys[1][d], a1);
            a2 = fmaf(wv, ys[2][d], a2);
            a3 = fmaf(wv, ys[3][d], a3);
        }
        sp[h][0][k] = a0; sp[h][1][k] = a1; sp[h][2][k] = a2; sp[h][3][k] = a3;
    }
    __syncthreads();

    // combine + squash: thread tid -> (b = tid>>6, k = tid&63)
    {
        const int b = tid >> 6, k = tid & 63;
        const float s = (sp[0][b][k] + sp[1][b][k]) + (sp[2][b][k] + sp[3][b][k]);
        float q = s*s;
        #pragma unroll
        for (int off = 16; off; off >>= 1) q += __shfl_xor_sync(0xffffffffu, q, off);
        const int w = tid >> 5;
        if ((tid & 31) == 0) qw[w] = q;
        __syncthreads();
        const float ri = rsqrtf(qw[2*b] + qw[2*b+1] + 1e-7f);
        const float o = s * ri;
        os[b][k] = o;
        if (phase == 2) out[((size_t)(bt+b)*NC_ + i)*DC_ + k] = o;
    }
    __syncthreads();

    // V phase: v[b][d] = log2e * sum_k Wt[i*64+k][d] * o[b][k]
    if (phase != 2) {
        const float L2E = 1.44269504f;
        for (int d = tid; d < D_; d += 256) {
            const float* wt = g_Wt + (size_t)(i*DC_)*D_ + d;
            float a0=0.f, a1=0.f, a2=0.f, a3=0.f;
            #pragma unroll 8
            for (int k = 0; k < 64; ++k) {
                const float wv = wt[(size_t)k*D_];
                a0 = fmaf(wv, os[0][k], a0);
                a1 = fmaf(wv, os[1][k], a1);
                a2 = fmaf(wv, os[2][k], a2);
                a3 = fmaf(wv, os[3][k], a3);
            }
            g_v[((size_t)(bt+0)*NC_ + i)*D_ + d] = a0 * L2E;
            g_v[((size_t)(bt+1)*NC_ + i)*D_ + d] = a1 * L2E;
            g_v[((size_t)(bt+2)*NC_ + i)*D_ + d] = a2 * L2E;
            g_v[((size_t)(bt+3)*NC_ + i)*D_ + d] = a3 * L2E;
        }
    }
}

// ---------------------------------------------------------------------------
// Kernel 3: main routing pass, R7 inner loop (v/y register-resident, FFMA2,
// ILP-2, raw EX2/RCP) but BALANCED: 148 blocks each own ~443 contiguous
// global rows (block spans <=2 batches); y flushed per batch-segment via
// smem merge + gmem atomicAdd into g_y (zeroed by k_caps).
// ---------------------------------------------------------------------------
__global__ void __launch_bounds__(256, 1) k_main(const float* __restrict__ x) {
    __shared__ __align__(16) float slab[4][NC_][D_];
    const int w    = threadIdx.x >> 5;
    const int lane = threadIdx.x & 31;
    const int tid  = threadIdx.x;
    const bool tl22 = (lane < 22);

    int rs = (int)(((long long)blockIdx.x     * RTOT) / GMAIN);
    const int re = (int)(((long long)(blockIdx.x+1) * RTOT) / GMAIN);

    while (rs < re) {
        const int batch  = rs >> 9;                       // rs / N_
        const int segEnd = min(re, (batch + 1) * N_);
        const int L      = segEnd - rs;

        // load this batch's v (pre-scaled by log2e) into registers
        const float* vb = g_v + (size_t)batch*NC_*D_;
        float2 vr[NC_][5];
        #pragma unroll
        for (int i = 0; i < NC_; ++i) {
            #pragma unroll
            for (int t = 0; t < 4; ++t)
                vr[i][t] = *(const float2*)(vb + i*D_ + 2*lane + 64*t);
            vr[i][4] = tl22 ? *(const float2*)(vb + i*D_ + 2*lane + 256)
                            : make_float2(0.f, 0.f);
        }
        float2 yr[NC_][5];
        #pragma unroll
        for (int i = 0; i < NC_; ++i)
            #pragma unroll
            for (int t = 0; t < 5; ++t) yr[i][t] = make_float2(0.f, 0.f);

        // warp w handles local rows {w + 8k}; ILP-2 pairs (l, l+8)
        int l = w;
        for (; l + 8 < L; l += 16) {
            const float* xrA = x + (size_t)(rs + l)*D_;
            const float* xrB = x + (size_t)(rs + l + 8)*D_;
            float2 xqA[5], xqB[5];
            #pragma unroll
            for (int t = 0; t < 4; ++t) {
                xqA[t] = *(const float2*)(xrA + 2*lane + 64*t);
                xqB[t] = *(const float2*)(xrB + 2*lane + 64*t);
            }
            xqA[4] = tl22 ? *(const float2*)(xrA + 2*lane + 256) : make_float2(0.f, 0.f);
            xqB[4] = tl22 ? *(const float2*)(xrB + 2*lane + 256) : make_float2(0.f, 0.f);

            float tlA[NC_], tlB[NC_];
            #pragma unroll
            for (int i = 0; i < NC_; ++i) {
                float2 aA = make_float2(0.f, 0.f), aB = make_float2(0.f, 0.f);
                #pragma unroll
                for (int t = 0; t < 5; ++t) {
                    aA = ffma2(xqA[t], vr[i][t], aA);
                    aB = ffma2(xqB[t], vr[i][t], aB);
                }
                tlA[i] = aA.x + aA.y;
                tlB[i] = aB.x + aB.y;
            }
            #pragma unroll
            for (int off = 16; off; off >>= 1) {
                #pragma unroll
                for (int i = 0; i < NC_; ++i) {
                    tlA[i] += __shfl_xor_sync(0xffffffffu, tlA[i], off);
                    tlB[i] += __shfl_xor_sync(0xffffffffu, tlB[i], off);
                }
            }
            #pragma unroll
            for (int i = 0; i < NC_; ++i) { tlA[i] = ex2_approx(tlA[i]); tlB[i] = ex2_approx(tlB[i]); }
            float sA = (((tlA[0]+tlA[1])+(tlA[2]+tlA[3]))+((tlA[4]+tlA[5])+(tlA[6]+tlA[7])))+(tlA[8]+tlA[9]);
            float sB = (((tlB[0]+tlB[1])+(tlB[2]+tlB[3]))+((tlB[4]+tlB[5])+(tlB[6]+tlB[7])))+(tlB[8]+tlB[9]);
            const float rA = rcp_approx(sA), rB = rcp_approx(sB);
            #pragma unroll
            for (int i = 0; i < NC_; ++i) {
                const float2 cA = make_float2(tlA[i]*rA, tlA[i]*rA);
                const float2 cB = make_float2(tlB[i]*rB, tlB[i]*rB);
                #pragma unroll
                for (int t = 0; t < 5; ++t)
                    yr[i][t] = ffma2(cB, xqB[t], ffma2(cA, xqA[t], yr[i][t]));
            }
        }
        if (l < L) {                                  // tail row
            const float* xr = x + (size_t)(rs + l)*D_;
            float2 xq[5];
            #pragma unroll
            for (int t = 0; t < 4; ++t) xq[t] = *(const float2*)(xr + 2*lane + 64*t);
            xq[4] = tl22 ? *(const float2*)(xr + 2*lane + 256) : make_float2(0.f, 0.f);
            float tl[NC_];
            #pragma unroll
            for (int i = 0; i < NC_; ++i) {
                float2 a = make_float2(0.f, 0.f);
                #pragma unroll
                for (int t = 0; t < 5; ++t) a = ffma2(xq[t], vr[i][t], a);
                tl[i] = a.x + a.y;
            }
            #pragma unroll
            for (int off = 16; off; off >>= 1)
                #pragma unroll
                for (int i = 0; i < NC_; ++i)
                    tl[i] += __shfl_xor_sync(0xffffffffu, tl[i], off);
            #pragma unroll
            for (int i = 0; i < NC_; ++i) tl[i] = ex2_approx(tl[i]);
            float s = (((tl[0]+tl[1])+(tl[2]+tl[3]))+((tl[4]+tl[5])+(tl[6]+tl[7])))+(tl[8]+tl[9]);
            const float r = rcp_approx(s);
            #pragma unroll
            for (int i = 0; i < NC_; ++i) {
                const float2 c = make_float2(tl[i]*r, tl[i]*r);
                #pragma unroll
                for (int t = 0; t < 5; ++t) yr[i][t] = ffma2(c, xq[t], yr[i][t]);
            }
        }

        // merge 8 warp partials then atomically flush this segment's y
        if (w < 4) {
            #pragma unroll
            for (int i = 0; i < NC_; ++i)
                #pragma unroll
                for (int t = 0; t < 5; ++t) {
                    const int d = 2*lane + 64*t;
                    if (d < D_) *(float2*)&slab[w][i][d] = yr[i][t];
                }
        }
        __syncthreads();
        if (w >= 4) {
            #pragma unroll
            for (int i = 0; i < NC_; ++i)
                #pragma unroll
                for (int t = 0; t < 5; ++t) {
                    const int d = 2*lane + 64*t;
                    if (d < D_) {
                        float2* p = (float2*)&slab[w-4][i][d];
                        float2 v0 = *p;
                        v0.x += yr[i][t].x; v0.y += yr[i][t].y;
                        *p = v0;
                    }
                }
        }
        __syncthreads();
        {
            float* yo = g_y + (size_t)batch*NC_*D_;
            const float* s0 = &slab[0][0][0];
            const float* s1 = &slab[1][0][0];
            const float* s2 = &slab[2][0][0];
            const float* s3 = &slab[3][0][0];
            for (int idx = tid; idx < NC_*D_; idx += 256)
                atomicAdd(&yo[idx], (s0[idx] + s1[idx]) + (s2[idx] + s3[idx]));
        }
        __syncthreads();   // slab safe to reuse for next segment
        rs = segEnd;
    }
}

// ---------------------------------------------------------------------------
extern "C" void kernel_launch(void* const* d_in, const int* in_sizes, int n_in,
                              void* d_out, int out_size) {
    const float* x = (const float*)d_in[0];
    const float* W = (const float*)d_in[1];
    if (n_in >= 2 && in_sizes[0] == D_*M_) {    // guard against input-order swap
        x = (const float*)d_in[1];
        W = (const float*)d_in[0];
    }
    float* out = (float*)d_out;

    // prep: colsum (512 blocks) + W transpose (200 blocks), fused
    k_prep<<<712, 256>>>(x, W);
    // iter 0: c uniform (=0.1) -> y = 0.1*colsum -> o0, v0 (also zero-inits g_y)
    k_caps<<<dim3(NC_, B_/4), 256>>>(W, out, 0);
    // iters 1..4: b = x.v -> softmax -> y(atomic);  y -> o -> v (zero y)
    for (int it = 1; it <= 4; ++it) {
        k_main<<<GMAIN, 256>>>(x);
        k_caps<<<dim3(NC_, B_/4), 256>>>(W, out, it == 4 ? 2 : 1);
    }
}